// round 4
// baseline (speedup 1.0000x reference)
#include <cuda_runtime.h>
#include <cuda_bf16.h>
#include <cstdint>

#define BB 16
#define TT 4096
#define DD 512
#define LL 1024

#define TILE_M 128
#define TILE_N 256
#define KSTEP 16
#define NSTEPS (DD / KSTEP)          // 32 k-steps per N-tile
#define NTILES (TT / TILE_N)         // 16
#define TOTSTEPS (NSTEPS * NTILES)   // 512
#define NSTAGE 4

#define A_HI_OFF 0
#define A_LO_OFF 4096
#define B_HI_OFF 8192
#define B_LO_OFF 16384
#define STAGE_BYTES 24576
#define SMEM_TOTAL (NSTAGE * STAGE_BYTES)   // 98304

__device__ __nv_bfloat16 g_xh[BB * TT * DD];   // 64 MB
__device__ __nv_bfloat16 g_xl[BB * TT * DD];   // 64 MB
__device__ __nv_bfloat16 g_qh[LL * DD];
__device__ __nv_bfloat16 g_ql[LL * DD];
__device__ float g_y[BB * TT];

// ---------------- PTX helpers ----------------
__device__ __forceinline__ uint32_t smem_u32(const void* p) {
    uint32_t a;
    asm("{ .reg .u64 t; cvta.to.shared.u64 t, %1; cvt.u32.u64 %0, t; }" : "=r"(a) : "l"(p));
    return a;
}
__device__ __forceinline__ void cp16(uint32_t dst, const void* src) {
    asm volatile("cp.async.cg.shared.global [%0], [%1], 16;" :: "r"(dst), "l"(src));
}
#define CP_COMMIT() asm volatile("cp.async.commit_group;" ::: "memory")
#define CP_WAIT2()  asm volatile("cp.async.wait_group 2;" ::: "memory")

__device__ __forceinline__ void ldsm4(uint32_t* r, uint32_t addr) {
    asm volatile("ldmatrix.sync.aligned.m8n8.x4.shared.b16 {%0,%1,%2,%3}, [%4];"
                 : "=r"(r[0]), "=r"(r[1]), "=r"(r[2]), "=r"(r[3]) : "r"(addr));
}
__device__ __forceinline__ void mma16816(float* c, const uint32_t* a, uint32_t b0, uint32_t b1) {
    asm volatile(
        "mma.sync.aligned.m16n8k16.row.col.f32.bf16.bf16.f32 "
        "{%0,%1,%2,%3}, {%4,%5,%6,%7}, {%8,%9}, {%0,%1,%2,%3};"
        : "+f"(c[0]), "+f"(c[1]), "+f"(c[2]), "+f"(c[3])
        : "r"(a[0]), "r"(a[1]), "r"(a[2]), "r"(a[3]), "r"(b0), "r"(b1));
}

// ---------------- precompute: bf16 hi/lo split of x and q, plus y ----------------
__global__ __launch_bounds__(256) void prep_kernel(const float* __restrict__ x,
                                                   const float* __restrict__ q,
                                                   const float* __restrict__ fc_w) {
    int wrow = blockIdx.x * 8 + (threadIdx.x >> 5);   // 0..66559
    int lane = threadIdx.x & 31;
    bool is_x = wrow < BB * TT;
    const float* src = is_x ? (x + (size_t)wrow * DD)
                            : (q + (size_t)(wrow - BB * TT) * DD);
    __nv_bfloat16* dh = is_x ? (g_xh + (size_t)wrow * DD)
                             : (g_qh + (size_t)(wrow - BB * TT) * DD);
    __nv_bfloat16* dl = is_x ? (g_xl + (size_t)wrow * DD)
                             : (g_ql + (size_t)(wrow - BB * TT) * DD);
    float s = 0.f;
#pragma unroll
    for (int c = 0; c < 4; c++) {
        int idx = c * 128 + lane * 4;
        float4 v = *(const float4*)(src + idx);
        if (is_x) {
            float4 w = *(const float4*)(fc_w + idx);
            s += v.x * w.x + v.y * w.y + v.z * w.z + v.w * w.w;
        }
        __nv_bfloat16 hx = __float2bfloat16(v.x), hy = __float2bfloat16(v.y);
        __nv_bfloat16 hz = __float2bfloat16(v.z), hw = __float2bfloat16(v.w);
        __nv_bfloat162 h01, h23, l01, l23;
        h01.x = hx; h01.y = hy; h23.x = hz; h23.y = hw;
        l01.x = __float2bfloat16(v.x - __bfloat162float(hx));
        l01.y = __float2bfloat16(v.y - __bfloat162float(hy));
        l23.x = __float2bfloat16(v.z - __bfloat162float(hz));
        l23.y = __float2bfloat16(v.w - __bfloat162float(hw));
        uint2 ph = make_uint2(*(uint32_t*)&h01, *(uint32_t*)&h23);
        uint2 pl = make_uint2(*(uint32_t*)&l01, *(uint32_t*)&l23);
        *(uint2*)(dh + idx) = ph;
        *(uint2*)(dl + idx) = pl;
    }
    if (is_x) {
#pragma unroll
        for (int o = 16; o; o >>= 1) s += __shfl_xor_sync(0xFFFFFFFFu, s, o);
        if (lane == 0) g_y[wrow] = s;
    }
}

// ---------------- main kernel ----------------
__global__ __launch_bounds__(256, 1) void attn_kernel(const float* __restrict__ fc_b,
                                                      float* __restrict__ out) {
    extern __shared__ char smem[];
    uint32_t sb = smem_u32(smem);
    int tid = threadIdx.x, wid = tid >> 5, lane = tid & 31;
    int warpM = wid & 3, warpN = wid >> 2;
    int ltile = blockIdx.x, b = blockIdx.y;

    // global source bases
    const __nv_bfloat16* qh = g_qh + (size_t)(ltile * TILE_M) * DD;
    const __nv_bfloat16* ql = g_ql + (size_t)(ltile * TILE_M) * DD;
    const __nv_bfloat16* xh = g_xh + (size_t)b * TT * DD;
    const __nv_bfloat16* xl = g_xl + (size_t)b * TT * DD;
    const float* yb = g_y + b * TT;

    // per-thread load assignment (6 x 16B per stage)
    int a_row = tid >> 1, a_half = tid & 1;               // 256 chunks for A (hi & lo)
    uint32_t a_dst = a_row * 32 + a_half * 16;
    size_t a_src = (size_t)a_row * DD + a_half * 8;       // + k0
    int b_row0 = tid >> 1, b_half0 = tid & 1;             // chunk tid
    int b_row1 = (tid + 256) >> 1, b_half1 = tid & 1;     // chunk tid+256
    uint32_t b_dst0 = b_row0 * 32 + b_half0 * 16;
    uint32_t b_dst1 = b_row1 * 32 + b_half1 * 16;

    // ldmatrix lane offsets
    uint32_t a_off0 = ((warpM * 32 + 0 + (lane & 15)) << 5) + ((lane >> 4) << 4);
    uint32_t a_off1 = ((warpM * 32 + 16 + (lane & 15)) << 5) + ((lane >> 4) << 4);
    int q4 = lane >> 3;
    uint32_t b_base = ((warpN * 128 + ((q4 >> 1) & 1) * 8 + (lane & 7)) << 5) + ((q4 & 1) << 4);

    // accumulators + softmax state
    float acc[2][16][4];
#pragma unroll
    for (int mt = 0; mt < 2; mt++)
#pragma unroll
        for (int g = 0; g < 16; g++)
#pragma unroll
            for (int i = 0; i < 4; i++) acc[mt][g][i] = 0.f;
    float m_run[2][2], Zp[2][2], Ap[2][2];
#pragma unroll
    for (int mt = 0; mt < 2; mt++)
#pragma unroll
        for (int h = 0; h < 2; h++) {
            m_run[mt][h] = __int_as_float(0xff800000);
            Zp[mt][h] = 0.f; Ap[mt][h] = 0.f;
        }

    // ---- stage issue helper (as lambda) ----
    auto issue = [&](int s) {
        int nt = s >> 5, kc = s & 31;
        int k0 = kc * KSTEP;
        uint32_t sbase = sb + (s & (NSTAGE - 1)) * STAGE_BYTES;
        cp16(sbase + A_HI_OFF + a_dst, qh + a_src + k0);
        cp16(sbase + A_LO_OFF + a_dst, ql + a_src + k0);
        size_t brow_base = (size_t)(nt * TILE_N) * DD + k0;
        cp16(sbase + B_HI_OFF + b_dst0, xh + brow_base + (size_t)b_row0 * DD + b_half0 * 8);
        cp16(sbase + B_HI_OFF + b_dst1, xh + brow_base + (size_t)b_row1 * DD + b_half1 * 8);
        cp16(sbase + B_LO_OFF + b_dst0, xl + brow_base + (size_t)b_row0 * DD + b_half0 * 8);
        cp16(sbase + B_LO_OFF + b_dst1, xl + brow_base + (size_t)b_row1 * DD + b_half1 * 8);
    };

    // prologue: stages 0..2
    for (int s = 0; s < NSTAGE - 1; s++) { issue(s); CP_COMMIT(); }

    for (int st = 0; st < TOTSTEPS; st++) {
        CP_WAIT2();
        __syncthreads();
        // issue stage st+3 (safe: all warps are past reads of buffer (st-1)&3)
        if (st + NSTAGE - 1 < TOTSTEPS) issue(st + NSTAGE - 1);
        CP_COMMIT();

        uint32_t sbase = sb + (st & (NSTAGE - 1)) * STAGE_BYTES;
        // A fragments
        uint32_t Ah[2][4], Al[2][4];
        ldsm4(Ah[0], sbase + A_HI_OFF + a_off0);
        ldsm4(Ah[1], sbase + A_HI_OFF + a_off1);
        ldsm4(Al[0], sbase + A_LO_OFF + a_off0);
        ldsm4(Al[1], sbase + A_LO_OFF + a_off1);
#pragma unroll
        for (int gp = 0; gp < 8; gp++) {
            uint32_t bh[4], bl[4];
            ldsm4(bh, sbase + B_HI_OFF + b_base + gp * 512);
            ldsm4(bl, sbase + B_LO_OFF + b_base + gp * 512);
#pragma unroll
            for (int g2 = 0; g2 < 2; g2++) {
                uint32_t bh0 = bh[2 * g2], bh1 = bh[2 * g2 + 1];
                uint32_t bl0 = bl[2 * g2], bl1 = bl[2 * g2 + 1];
#pragma unroll
                for (int mt = 0; mt < 2; mt++) {
                    float* c = acc[mt][gp * 2 + g2];
                    mma16816(c, Ah[mt], bh0, bh1);
                    mma16816(c, Ah[mt], bl0, bl1);
                    mma16816(c, Al[mt], bh0, bh1);
                }
            }
        }

        if ((st & (NSTEPS - 1)) == NSTEPS - 1) {
            // ---- N-tile epilogue: online softmax ----
            int nt = st >> 5;
            float rmax[2][2];
#pragma unroll
            for (int mt = 0; mt < 2; mt++)
#pragma unroll
                for (int h = 0; h < 2; h++) {
                    float r = __int_as_float(0xff800000);
#pragma unroll
                    for (int g = 0; g < 16; g++)
                        r = fmaxf(r, fmaxf(acc[mt][g][2 * h], acc[mt][g][2 * h + 1]));
                    rmax[mt][h] = r;
                }
#pragma unroll
            for (int mt = 0; mt < 2; mt++)
#pragma unroll
                for (int h = 0; h < 2; h++) {
                    float r = rmax[mt][h];
                    r = fmaxf(r, __shfl_xor_sync(0xFFFFFFFFu, r, 1));
                    r = fmaxf(r, __shfl_xor_sync(0xFFFFFFFFu, r, 2));
                    float mn = fmaxf(m_run[mt][h], r);
                    float sc = __expf(m_run[mt][h] - mn);
                    Zp[mt][h] *= sc; Ap[mt][h] *= sc;
                    m_run[mt][h] = mn;
                }
            const float2* yrow = (const float2*)(yb + nt * TILE_N + warpN * 128);
#pragma unroll
            for (int g = 0; g < 16; g++) {
                float2 yv = __ldg(&yrow[g * 4 + (lane & 3)]);
#pragma unroll
                for (int mt = 0; mt < 2; mt++)
#pragma unroll
                    for (int h = 0; h < 2; h++) {
                        float e0 = __expf(acc[mt][g][2 * h]     - m_run[mt][h]);
                        float e1 = __expf(acc[mt][g][2 * h + 1] - m_run[mt][h]);
                        Zp[mt][h] += e0 + e1;
                        Ap[mt][h] += e0 * yv.x + e1 * yv.y;
                        acc[mt][g][2 * h] = 0.f;
                        acc[mt][g][2 * h + 1] = 0.f;
                    }
            }
        }
    }

    // ---- final reductions ----
#pragma unroll
    for (int mt = 0; mt < 2; mt++)
#pragma unroll
        for (int h = 0; h < 2; h++) {
            float z = Zp[mt][h], a = Ap[mt][h];
            z += __shfl_xor_sync(0xFFFFFFFFu, z, 1);
            z += __shfl_xor_sync(0xFFFFFFFFu, z, 2);
            a += __shfl_xor_sync(0xFFFFFFFFu, a, 1);
            a += __shfl_xor_sync(0xFFFFFFFFu, a, 2);
            Zp[mt][h] = z; Ap[mt][h] = a;
        }
    __syncthreads();   // stage smem no longer needed
    float* msm = (float*)smem;          // 256
    float* zsm = msm + 256;             // 256
    float* asm2 = msm + 512;            // 256
    if ((lane & 3) == 0) {
#pragma unroll
        for (int mt = 0; mt < 2; mt++)
#pragma unroll
            for (int h = 0; h < 2; h++) {
                int row = warpM * 32 + mt * 16 + (lane >> 2) + h * 8;
                int i = row * 2 + warpN;
                msm[i] = m_run[mt][h];
                zsm[i] = Zp[mt][h];
                asm2[i] = Ap[mt][h];
            }
    }
    __syncthreads();
    if (tid < TILE_M) {
        float m0 = msm[tid * 2], m1 = msm[tid * 2 + 1];
        float mstar = fmaxf(m0, m1);
        float e0 = __expf(m0 - mstar), e1 = __expf(m1 - mstar);
        float Z = zsm[tid * 2] * e0 + zsm[tid * 2 + 1] * e1;
        float A = asm2[tid * 2] * e0 + asm2[tid * 2 + 1] * e1;
        out[(size_t)b * LL + ltile * TILE_M + tid] = A / Z + __ldg(fc_b);
    }
}

// ---------------- host ----------------
extern "C" void kernel_launch(void* const* d_in, const int* in_sizes, int n_in,
                              void* d_out, int out_size) {
    const float* x    = (const float*)d_in[0];
    const float* q    = (const float*)d_in[1];
    const float* fc_w = (const float*)d_in[2];
    const float* fc_b = (const float*)d_in[3];
    float* out = (float*)d_out;

    prep_kernel<<<(BB * TT + LL) / 8, 256>>>(x, q, fc_w);

    static bool attr_set = false;
    cudaFuncSetAttribute(attn_kernel, cudaFuncAttributeMaxDynamicSharedMemorySize, SMEM_TOTAL);
    (void)attr_set;
    attn_kernel<<<dim3(LL / TILE_M, BB), 256, SMEM_TOTAL>>>(fc_b, out);
}

// round 5
// speedup vs baseline: 1.0823x; 1.0823x over previous
#include <cuda_runtime.h>
#include <cuda_bf16.h>
#include <cstdint>

#define BB 16
#define TT 4096
#define DD 512
#define LL 1024

#define TILE_M 128
#define TILE_N 256
#define KSTEP 16
#define NSTEPS (DD / KSTEP)          // 32 k-steps per N-tile
#define NTILES (TT / TILE_N)         // 16
#define TOTSTEPS (NSTEPS * NTILES)   // 512
#define NSTAGE 4

#define A_HI_OFF 0
#define A_LO_OFF 4096
#define B_HI_OFF 8192
#define B_LO_OFF 16384
#define STAGE_BYTES 24576
#define SMEM_TOTAL (NSTAGE * STAGE_BYTES)   // 98304

#define NTHREADS 512

__device__ __nv_bfloat16 g_xh[BB * TT * DD];   // 64 MB
__device__ __nv_bfloat16 g_xl[BB * TT * DD];   // 64 MB
__device__ __nv_bfloat16 g_qh[LL * DD];
__device__ __nv_bfloat16 g_ql[LL * DD];
__device__ float g_y[BB * TT];

// ---------------- PTX helpers ----------------
__device__ __forceinline__ uint32_t smem_u32(const void* p) {
    uint32_t a;
    asm("{ .reg .u64 t; cvta.to.shared.u64 t, %1; cvt.u32.u64 %0, t; }" : "=r"(a) : "l"(p));
    return a;
}
__device__ __forceinline__ void cp16(uint32_t dst, const void* src) {
    asm volatile("cp.async.cg.shared.global [%0], [%1], 16;" :: "r"(dst), "l"(src));
}
#define CP_COMMIT() asm volatile("cp.async.commit_group;" ::: "memory")
#define CP_WAIT2()  asm volatile("cp.async.wait_group 2;" ::: "memory")

__device__ __forceinline__ void ldsm4(uint32_t* r, uint32_t addr) {
    asm volatile("ldmatrix.sync.aligned.m8n8.x4.shared.b16 {%0,%1,%2,%3}, [%4];"
                 : "=r"(r[0]), "=r"(r[1]), "=r"(r[2]), "=r"(r[3]) : "r"(addr));
}
__device__ __forceinline__ void mma16816(float* c, const uint32_t* a, uint32_t b0, uint32_t b1) {
    asm volatile(
        "mma.sync.aligned.m16n8k16.row.col.f32.bf16.bf16.f32 "
        "{%0,%1,%2,%3}, {%4,%5,%6,%7}, {%8,%9}, {%0,%1,%2,%3};"
        : "+f"(c[0]), "+f"(c[1]), "+f"(c[2]), "+f"(c[3])
        : "r"(a[0]), "r"(a[1]), "r"(a[2]), "r"(a[3]), "r"(b0), "r"(b1));
}

// ---------------- precompute: bf16 hi/lo split of x and q, plus y ----------------
__global__ __launch_bounds__(256) void prep_kernel(const float* __restrict__ x,
                                                   const float* __restrict__ q,
                                                   const float* __restrict__ fc_w) {
    int wrow = blockIdx.x * 8 + (threadIdx.x >> 5);
    int lane = threadIdx.x & 31;
    bool is_x = wrow < BB * TT;
    const float* src = is_x ? (x + (size_t)wrow * DD)
                            : (q + (size_t)(wrow - BB * TT) * DD);
    __nv_bfloat16* dh = is_x ? (g_xh + (size_t)wrow * DD)
                             : (g_qh + (size_t)(wrow - BB * TT) * DD);
    __nv_bfloat16* dl = is_x ? (g_xl + (size_t)wrow * DD)
                             : (g_ql + (size_t)(wrow - BB * TT) * DD);
    float s = 0.f;
#pragma unroll
    for (int c = 0; c < 4; c++) {
        int idx = c * 128 + lane * 4;
        float4 v = *(const float4*)(src + idx);
        if (is_x) {
            float4 w = *(const float4*)(fc_w + idx);
            s += v.x * w.x + v.y * w.y + v.z * w.z + v.w * w.w;
        }
        __nv_bfloat16 hx = __float2bfloat16(v.x), hy = __float2bfloat16(v.y);
        __nv_bfloat16 hz = __float2bfloat16(v.z), hw = __float2bfloat16(v.w);
        __nv_bfloat162 h01, h23, l01, l23;
        h01.x = hx; h01.y = hy; h23.x = hz; h23.y = hw;
        l01.x = __float2bfloat16(v.x - __bfloat162float(hx));
        l01.y = __float2bfloat16(v.y - __bfloat162float(hy));
        l23.x = __float2bfloat16(v.z - __bfloat162float(hz));
        l23.y = __float2bfloat16(v.w - __bfloat162float(hw));
        uint2 ph = make_uint2(*(uint32_t*)&h01, *(uint32_t*)&h23);
        uint2 pl = make_uint2(*(uint32_t*)&l01, *(uint32_t*)&l23);
        *(uint2*)(dh + idx) = ph;
        *(uint2*)(dl + idx) = pl;
    }
    if (is_x) {
#pragma unroll
        for (int o = 16; o; o >>= 1) s += __shfl_xor_sync(0xFFFFFFFFu, s, o);
        if (lane == 0) g_y[wrow] = s;
    }
}

// ---------------- main kernel: 16 warps, warp tile 32x64 ----------------
__global__ __launch_bounds__(NTHREADS, 1) void attn_kernel(const float* __restrict__ fc_b,
                                                           float* __restrict__ out) {
    extern __shared__ char smem[];
    uint32_t sb = smem_u32(smem);
    int tid = threadIdx.x, wid = tid >> 5, lane = tid & 31;
    int warpM = wid & 3, warpN = wid >> 2;      // 4 x 4 warps
    int ltile = blockIdx.x, b = blockIdx.y;

    const __nv_bfloat16* qh = g_qh + (size_t)(ltile * TILE_M) * DD;
    const __nv_bfloat16* ql = g_ql + (size_t)(ltile * TILE_M) * DD;
    const __nv_bfloat16* xh = g_xh + (size_t)b * TT * DD;
    const __nv_bfloat16* xl = g_xl + (size_t)b * TT * DD;
    const float* yb = g_y + b * TT;

    // ---- per-thread load assignment: 1 A chunk + 2 B chunks (16B each) ----
    int ac = tid & 255;
    int a_row = ac >> 1, a_half = ac & 1;
    uint32_t a_dst = (tid < 256 ? A_HI_OFF : A_LO_OFF) + a_row * 32 + a_half * 16;
    const __nv_bfloat16* a_srcbase = (tid < 256 ? qh : ql) + (size_t)a_row * DD + a_half * 8;
    int b_row = tid >> 1, b_half = tid & 1;
    uint32_t b_dst = b_row * 32 + b_half * 16;
    size_t b_rowoff = (size_t)b_row * DD + b_half * 8;

    // ---- ldmatrix lane offsets ----
    uint32_t a_off0 = ((warpM * 32 + 0 + (lane & 15)) << 5) + ((lane >> 4) << 4);
    uint32_t a_off1 = ((warpM * 32 + 16 + (lane & 15)) << 5) + ((lane >> 4) << 4);
    int q4 = lane >> 3;
    uint32_t b_base = ((warpN * 64 + ((q4 >> 1) & 1) * 8 + (lane & 7)) << 5) + ((q4 & 1) << 4);

    // ---- accumulators + softmax state ----
    float acc[2][8][4];
#pragma unroll
    for (int mt = 0; mt < 2; mt++)
#pragma unroll
        for (int g = 0; g < 8; g++)
#pragma unroll
            for (int i = 0; i < 4; i++) acc[mt][g][i] = 0.f;
    float m_run[2][2], Zp[2][2], Ap[2][2];
#pragma unroll
    for (int mt = 0; mt < 2; mt++)
#pragma unroll
        for (int h = 0; h < 2; h++) {
            m_run[mt][h] = __int_as_float(0xff800000);
            Zp[mt][h] = 0.f; Ap[mt][h] = 0.f;
        }

    auto issue = [&](int s) {
        int nt = s >> 5, kc = s & 31;
        int k0 = kc * KSTEP;
        uint32_t sbase = sb + (s & (NSTAGE - 1)) * STAGE_BYTES;
        cp16(sbase + a_dst, a_srcbase + k0);
        size_t bsrc = (size_t)(nt * TILE_N) * DD + k0 + b_rowoff;
        cp16(sbase + B_HI_OFF + b_dst, xh + bsrc);
        cp16(sbase + B_LO_OFF + b_dst, xl + bsrc);
    };

    for (int s = 0; s < NSTAGE - 1; s++) { issue(s); CP_COMMIT(); }

    for (int st = 0; st < TOTSTEPS; st++) {
        CP_WAIT2();
        __syncthreads();
        if (st + NSTAGE - 1 < TOTSTEPS) issue(st + NSTAGE - 1);
        CP_COMMIT();

        uint32_t sbase = sb + (st & (NSTAGE - 1)) * STAGE_BYTES;
        uint32_t Ah[2][4], Al[2][4];
        ldsm4(Ah[0], sbase + A_HI_OFF + a_off0);
        ldsm4(Ah[1], sbase + A_HI_OFF + a_off1);
        ldsm4(Al[0], sbase + A_LO_OFF + a_off0);
        ldsm4(Al[1], sbase + A_LO_OFF + a_off1);
#pragma unroll
        for (int gp = 0; gp < 4; gp++) {
            uint32_t bh[4], bl[4];
            ldsm4(bh, sbase + B_HI_OFF + b_base + gp * 512);
            ldsm4(bl, sbase + B_LO_OFF + b_base + gp * 512);
#pragma unroll
            for (int g2 = 0; g2 < 2; g2++) {
                uint32_t bh0 = bh[2 * g2], bh1 = bh[2 * g2 + 1];
                uint32_t bl0 = bl[2 * g2], bl1 = bl[2 * g2 + 1];
#pragma unroll
                for (int mt = 0; mt < 2; mt++) {
                    float* c = acc[mt][gp * 2 + g2];
                    mma16816(c, Ah[mt], bh0, bh1);
                    mma16816(c, Ah[mt], bl0, bl1);
                    mma16816(c, Al[mt], bh0, bh1);
                }
            }
        }

        if ((st & (NSTEPS - 1)) == NSTEPS - 1) {
            // ---- N-tile epilogue: online softmax (warp-local, 64-col slice) ----
            int nt = st >> 5;
#pragma unroll
            for (int mt = 0; mt < 2; mt++)
#pragma unroll
                for (int h = 0; h < 2; h++) {
                    float r = __int_as_float(0xff800000);
#pragma unroll
                    for (int g = 0; g < 8; g++)
                        r = fmaxf(r, fmaxf(acc[mt][g][2 * h], acc[mt][g][2 * h + 1]));
                    r = fmaxf(r, __shfl_xor_sync(0xFFFFFFFFu, r, 1));
                    r = fmaxf(r, __shfl_xor_sync(0xFFFFFFFFu, r, 2));
                    float mn = fmaxf(m_run[mt][h], r);
                    float sc = __expf(m_run[mt][h] - mn);
                    Zp[mt][h] *= sc; Ap[mt][h] *= sc;
                    m_run[mt][h] = mn;
                }
            const float2* yrow = (const float2*)(yb + nt * TILE_N + warpN * 64);
#pragma unroll
            for (int g = 0; g < 8; g++) {
                float2 yv = __ldg(&yrow[g * 4 + (lane & 3)]);
#pragma unroll
                for (int mt = 0; mt < 2; mt++)
#pragma unroll
                    for (int h = 0; h < 2; h++) {
                        float e0 = __expf(acc[mt][g][2 * h]     - m_run[mt][h]);
                        float e1 = __expf(acc[mt][g][2 * h + 1] - m_run[mt][h]);
                        Zp[mt][h] += e0 + e1;
                        Ap[mt][h] += e0 * yv.x + e1 * yv.y;
                        acc[mt][g][2 * h] = 0.f;
                        acc[mt][g][2 * h + 1] = 0.f;
                    }
            }
        }
    }

    // ---- final reductions: lanes within quad, then across 4 warpN warps ----
#pragma unroll
    for (int mt = 0; mt < 2; mt++)
#pragma unroll
        for (int h = 0; h < 2; h++) {
            float z = Zp[mt][h], a = Ap[mt][h];
            z += __shfl_xor_sync(0xFFFFFFFFu, z, 1);
            z += __shfl_xor_sync(0xFFFFFFFFu, z, 2);
            a += __shfl_xor_sync(0xFFFFFFFFu, a, 1);
            a += __shfl_xor_sync(0xFFFFFFFFu, a, 2);
            Zp[mt][h] = z; Ap[mt][h] = a;
        }
    __syncthreads();
    float* msm  = (float*)smem;            // 128*4
    float* zsm  = msm + 512;               // 128*4
    float* asm2 = msm + 1024;              // 128*4
    if ((lane & 3) == 0) {
#pragma unroll
        for (int mt = 0; mt < 2; mt++)
#pragma unroll
            for (int h = 0; h < 2; h++) {
                int row = warpM * 32 + mt * 16 + (lane >> 2) + h * 8;
                int i = row * 4 + warpN;
                msm[i] = m_run[mt][h];
                zsm[i] = Zp[mt][h];
                asm2[i] = Ap[mt][h];
            }
    }
    __syncthreads();
    if (tid < TILE_M) {
        float m0 = msm[tid * 4], m1 = msm[tid * 4 + 1];
        float m2 = msm[tid * 4 + 2], m3 = msm[tid * 4 + 3];
        float mstar = fmaxf(fmaxf(m0, m1), fmaxf(m2, m3));
        float e0 = __expf(m0 - mstar), e1 = __expf(m1 - mstar);
        float e2 = __expf(m2 - mstar), e3 = __expf(m3 - mstar);
        float Z = zsm[tid * 4] * e0 + zsm[tid * 4 + 1] * e1
                + zsm[tid * 4 + 2] * e2 + zsm[tid * 4 + 3] * e3;
        float A = asm2[tid * 4] * e0 + asm2[tid * 4 + 1] * e1
                + asm2[tid * 4 + 2] * e2 + asm2[tid * 4 + 3] * e3;
        out[(size_t)b * LL + ltile * TILE_M + tid] = A / Z + __ldg(fc_b);
    }
}

// ---------------- host ----------------
extern "C" void kernel_launch(void* const* d_in, const int* in_sizes, int n_in,
                              void* d_out, int out_size) {
    const float* x    = (const float*)d_in[0];
    const float* q    = (const float*)d_in[1];
    const float* fc_w = (const float*)d_in[2];
    const float* fc_b = (const float*)d_in[3];
    float* out = (float*)d_out;

    prep_kernel<<<(BB * TT + LL) / 8, 256>>>(x, q, fc_w);

    cudaFuncSetAttribute(attn_kernel, cudaFuncAttributeMaxDynamicSharedMemorySize, SMEM_TOTAL);
    attn_kernel<<<dim3(LL / TILE_M, BB), NTHREADS, SMEM_TOTAL>>>(fc_b, out);
}

// round 6
// speedup vs baseline: 1.2421x; 1.1476x over previous
#include <cuda_runtime.h>
#include <cuda_bf16.h>
#include <cstdint>

#define BB 16
#define TT 4096
#define DD 512
#define LL 1024

#define TILE_M 128
#define TILE_N 256
#define KSTEP 16
#define NSTEPS (DD / KSTEP)          // 32 k-steps per N-tile
#define NTILES (TT / TILE_N)         // 16
#define TOTSTEPS (NSTEPS * NTILES)   // 512
#define NSTAGE 4

#define A_HI_OFF 0
#define A_LO_OFF 4096
#define B_HI_OFF 8192
#define B_LO_OFF 16384
#define STAGE_BYTES 24576
#define SMEM_TOTAL (NSTAGE * STAGE_BYTES)   // 98304

#define NTHREADS 512

// XOR swizzle: row stride 32B, chunk (16B) index XORed with bit2 of row.
// Makes every ldmatrix 8-row phase cover all 32 banks.
#define SWZ(row, chunk) ((uint32_t)((row) * 32 + (((chunk) ^ (((row) >> 2) & 1)) << 4)))

__device__ __nv_bfloat16 g_xh[BB * TT * DD];   // 64 MB
__device__ __nv_bfloat16 g_xl[BB * TT * DD];   // 64 MB
__device__ __nv_bfloat16 g_qh[LL * DD];
__device__ __nv_bfloat16 g_ql[LL * DD];
__device__ float g_y[BB * TT];

// ---------------- PTX helpers ----------------
__device__ __forceinline__ uint32_t smem_u32(const void* p) {
    uint32_t a;
    asm("{ .reg .u64 t; cvta.to.shared.u64 t, %1; cvt.u32.u64 %0, t; }" : "=r"(a) : "l"(p));
    return a;
}
__device__ __forceinline__ void cp16(uint32_t dst, const void* src) {
    asm volatile("cp.async.cg.shared.global [%0], [%1], 16;" :: "r"(dst), "l"(src));
}
#define CP_COMMIT() asm volatile("cp.async.commit_group;" ::: "memory")
#define CP_WAIT2()  asm volatile("cp.async.wait_group 2;" ::: "memory")

__device__ __forceinline__ void ldsm4(uint32_t* r, uint32_t addr) {
    asm volatile("ldmatrix.sync.aligned.m8n8.x4.shared.b16 {%0,%1,%2,%3}, [%4];"
                 : "=r"(r[0]), "=r"(r[1]), "=r"(r[2]), "=r"(r[3]) : "r"(addr));
}
__device__ __forceinline__ void mma16816(float* c, const uint32_t* a, uint32_t b0, uint32_t b1) {
    asm volatile(
        "mma.sync.aligned.m16n8k16.row.col.f32.bf16.bf16.f32 "
        "{%0,%1,%2,%3}, {%4,%5,%6,%7}, {%8,%9}, {%0,%1,%2,%3};"
        : "+f"(c[0]), "+f"(c[1]), "+f"(c[2]), "+f"(c[3])
        : "r"(a[0]), "r"(a[1]), "r"(a[2]), "r"(a[3]), "r"(b0), "r"(b1));
}

// ---------------- precompute: bf16 hi/lo split of x and q, plus y ----------------
__global__ __launch_bounds__(256) void prep_kernel(const float* __restrict__ x,
                                                   const float* __restrict__ q,
                                                   const float* __restrict__ fc_w) {
    int wrow = blockIdx.x * 8 + (threadIdx.x >> 5);
    int lane = threadIdx.x & 31;
    bool is_x = wrow < BB * TT;
    const float* src = is_x ? (x + (size_t)wrow * DD)
                            : (q + (size_t)(wrow - BB * TT) * DD);
    __nv_bfloat16* dh = is_x ? (g_xh + (size_t)wrow * DD)
                             : (g_qh + (size_t)(wrow - BB * TT) * DD);
    __nv_bfloat16* dl = is_x ? (g_xl + (size_t)wrow * DD)
                             : (g_ql + (size_t)(wrow - BB * TT) * DD);
    float s = 0.f;
#pragma unroll
    for (int c = 0; c < 4; c++) {
        int idx = c * 128 + lane * 4;
        float4 v = *(const float4*)(src + idx);
        if (is_x) {
            float4 w = *(const float4*)(fc_w + idx);
            s += v.x * w.x + v.y * w.y + v.z * w.z + v.w * w.w;
        }
        __nv_bfloat16 hx = __float2bfloat16(v.x), hy = __float2bfloat16(v.y);
        __nv_bfloat16 hz = __float2bfloat16(v.z), hw = __float2bfloat16(v.w);
        __nv_bfloat162 h01, h23, l01, l23;
        h01.x = hx; h01.y = hy; h23.x = hz; h23.y = hw;
        l01.x = __float2bfloat16(v.x - __bfloat162float(hx));
        l01.y = __float2bfloat16(v.y - __bfloat162float(hy));
        l23.x = __float2bfloat16(v.z - __bfloat162float(hz));
        l23.y = __float2bfloat16(v.w - __bfloat162float(hw));
        uint2 ph = make_uint2(*(uint32_t*)&h01, *(uint32_t*)&h23);
        uint2 pl = make_uint2(*(uint32_t*)&l01, *(uint32_t*)&l23);
        *(uint2*)(dh + idx) = ph;
        *(uint2*)(dl + idx) = pl;
    }
    if (is_x) {
#pragma unroll
        for (int o = 16; o; o >>= 1) s += __shfl_xor_sync(0xFFFFFFFFu, s, o);
        if (lane == 0) g_y[wrow] = s;
    }
}

// ---------------- main kernel: 16 warps, warp tile 32x64, swizzled smem ----------------
__global__ __launch_bounds__(NTHREADS, 1) void attn_kernel(const float* __restrict__ fc_b,
                                                           float* __restrict__ out) {
    extern __shared__ char smem[];
    uint32_t sb = smem_u32(smem);
    int tid = threadIdx.x, wid = tid >> 5, lane = tid & 31;
    int warpM = wid & 3, warpN = wid >> 2;      // 4 x 4 warps
    int ltile = blockIdx.x, b = blockIdx.y;

    const __nv_bfloat16* qh = g_qh + (size_t)(ltile * TILE_M) * DD;
    const __nv_bfloat16* ql = g_ql + (size_t)(ltile * TILE_M) * DD;
    const __nv_bfloat16* xh = g_xh + (size_t)b * TT * DD;
    const __nv_bfloat16* xl = g_xl + (size_t)b * TT * DD;
    const float* yb = g_y + b * TT;

    // ---- per-thread load assignment: 1 A chunk + 2 B chunks (16B each), swizzled dst ----
    int ac = tid & 255;
    int a_row = ac >> 1, a_half = ac & 1;
    uint32_t a_dst = (tid < 256 ? A_HI_OFF : A_LO_OFF) + SWZ(a_row, a_half);
    const __nv_bfloat16* a_srcbase = (tid < 256 ? qh : ql) + (size_t)a_row * DD + a_half * 8;
    int b_row = tid >> 1, b_half = tid & 1;
    uint32_t b_dst = SWZ(b_row, b_half);
    size_t b_rowoff = (size_t)b_row * DD + b_half * 8;

    // ---- ldmatrix lane offsets (swizzled; +16-row strides preserve swizzle parity) ----
    int a_r0 = warpM * 32 + (lane & 15);
    uint32_t a_off0 = SWZ(a_r0, lane >> 4);
    uint32_t a_off1 = SWZ(a_r0 + 16, lane >> 4);
    int q4 = lane >> 3;
    int b_r0 = warpN * 64 + ((q4 >> 1) & 1) * 8 + (lane & 7);
    uint32_t b_base = SWZ(b_r0, q4 & 1);

    // ---- accumulators + softmax state ----
    float acc[2][8][4];
#pragma unroll
    for (int mt = 0; mt < 2; mt++)
#pragma unroll
        for (int g = 0; g < 8; g++)
#pragma unroll
            for (int i = 0; i < 4; i++) acc[mt][g][i] = 0.f;
    float m_run[2][2], Zp[2][2], Ap[2][2];
#pragma unroll
    for (int mt = 0; mt < 2; mt++)
#pragma unroll
        for (int h = 0; h < 2; h++) {
            m_run[mt][h] = __int_as_float(0xff800000);
            Zp[mt][h] = 0.f; Ap[mt][h] = 0.f;
        }

    auto issue = [&](int s) {
        int nt = s >> 5, kc = s & 31;
        int k0 = kc * KSTEP;
        uint32_t sbase = sb + (s & (NSTAGE - 1)) * STAGE_BYTES;
        cp16(sbase + a_dst, a_srcbase + k0);
        size_t bsrc = (size_t)(nt * TILE_N) * DD + k0 + b_rowoff;
        cp16(sbase + B_HI_OFF + b_dst, xh + bsrc);
        cp16(sbase + B_LO_OFF + b_dst, xl + bsrc);
    };

    for (int s = 0; s < NSTAGE - 1; s++) { issue(s); CP_COMMIT(); }

    for (int st = 0; st < TOTSTEPS; st++) {
        CP_WAIT2();
        __syncthreads();
        if (st + NSTAGE - 1 < TOTSTEPS) issue(st + NSTAGE - 1);
        CP_COMMIT();

        uint32_t sbase = sb + (st & (NSTAGE - 1)) * STAGE_BYTES;
        uint32_t Ah[2][4], Al[2][4];
        ldsm4(Ah[0], sbase + A_HI_OFF + a_off0);
        ldsm4(Ah[1], sbase + A_HI_OFF + a_off1);
        ldsm4(Al[0], sbase + A_LO_OFF + a_off0);
        ldsm4(Al[1], sbase + A_LO_OFF + a_off1);
#pragma unroll
        for (int gp = 0; gp < 4; gp++) {
            uint32_t bh[4], bl[4];
            ldsm4(bh, sbase + B_HI_OFF + b_base + gp * 512);
            ldsm4(bl, sbase + B_LO_OFF + b_base + gp * 512);
#pragma unroll
            for (int g2 = 0; g2 < 2; g2++) {
                uint32_t bh0 = bh[2 * g2], bh1 = bh[2 * g2 + 1];
                uint32_t bl0 = bl[2 * g2], bl1 = bl[2 * g2 + 1];
#pragma unroll
                for (int mt = 0; mt < 2; mt++) {
                    float* c = acc[mt][gp * 2 + g2];
                    mma16816(c, Ah[mt], bh0, bh1);
                    mma16816(c, Ah[mt], bl0, bl1);
                    mma16816(c, Al[mt], bh0, bh1);
                }
            }
        }

        if ((st & (NSTEPS - 1)) == NSTEPS - 1) {
            // ---- N-tile epilogue: online softmax (warp-local, 64-col slice) ----
            int nt = st >> 5;
#pragma unroll
            for (int mt = 0; mt < 2; mt++)
#pragma unroll
                for (int h = 0; h < 2; h++) {
                    float r = __int_as_float(0xff800000);
#pragma unroll
                    for (int g = 0; g < 8; g++)
                        r = fmaxf(r, fmaxf(acc[mt][g][2 * h], acc[mt][g][2 * h + 1]));
                    r = fmaxf(r, __shfl_xor_sync(0xFFFFFFFFu, r, 1));
                    r = fmaxf(r, __shfl_xor_sync(0xFFFFFFFFu, r, 2));
                    float mn = fmaxf(m_run[mt][h], r);
                    float sc = __expf(m_run[mt][h] - mn);
                    Zp[mt][h] *= sc; Ap[mt][h] *= sc;
                    m_run[mt][h] = mn;
                }
            const float2* yrow = (const float2*)(yb + nt * TILE_N + warpN * 64);
#pragma unroll
            for (int g = 0; g < 8; g++) {
                float2 yv = __ldg(&yrow[g * 4 + (lane & 3)]);
#pragma unroll
                for (int mt = 0; mt < 2; mt++)
#pragma unroll
                    for (int h = 0; h < 2; h++) {
                        float e0 = __expf(acc[mt][g][2 * h]     - m_run[mt][h]);
                        float e1 = __expf(acc[mt][g][2 * h + 1] - m_run[mt][h]);
                        Zp[mt][h] += e0 + e1;
                        Ap[mt][h] += e0 * yv.x + e1 * yv.y;
                        acc[mt][g][2 * h] = 0.f;
                        acc[mt][g][2 * h + 1] = 0.f;
                    }
            }
        }
    }

    // ---- final reductions: lanes within quad, then across 4 warpN warps ----
#pragma unroll
    for (int mt = 0; mt < 2; mt++)
#pragma unroll
        for (int h = 0; h < 2; h++) {
            float z = Zp[mt][h], a = Ap[mt][h];
            z += __shfl_xor_sync(0xFFFFFFFFu, z, 1);
            z += __shfl_xor_sync(0xFFFFFFFFu, z, 2);
            a += __shfl_xor_sync(0xFFFFFFFFu, a, 1);
            a += __shfl_xor_sync(0xFFFFFFFFu, a, 2);
            Zp[mt][h] = z; Ap[mt][h] = a;
        }
    __syncthreads();
    float* msm  = (float*)smem;            // 128*4
    float* zsm  = msm + 512;               // 128*4
    float* asm2 = msm + 1024;              // 128*4
    if ((lane & 3) == 0) {
#pragma unroll
        for (int mt = 0; mt < 2; mt++)
#pragma unroll
            for (int h = 0; h < 2; h++) {
                int row = warpM * 32 + mt * 16 + (lane >> 2) + h * 8;
                int i = row * 4 + warpN;
                msm[i] = m_run[mt][h];
                zsm[i] = Zp[mt][h];
                asm2[i] = Ap[mt][h];
            }
    }
    __syncthreads();
    if (tid < TILE_M) {
        float m0 = msm[tid * 4], m1 = msm[tid * 4 + 1];
        float m2 = msm[tid * 4 + 2], m3 = msm[tid * 4 + 3];
        float mstar = fmaxf(fmaxf(m0, m1), fmaxf(m2, m3));
        float e0 = __expf(m0 - mstar), e1 = __expf(m1 - mstar);
        float e2 = __expf(m2 - mstar), e3 = __expf(m3 - mstar);
        float Z = zsm[tid * 4] * e0 + zsm[tid * 4 + 1] * e1
                + zsm[tid * 4 + 2] * e2 + zsm[tid * 4 + 3] * e3;
        float A = asm2[tid * 4] * e0 + asm2[tid * 4 + 1] * e1
                + asm2[tid * 4 + 2] * e2 + asm2[tid * 4 + 3] * e3;
        out[(size_t)b * LL + ltile * TILE_M + tid] = A / Z + __ldg(fc_b);
    }
}

// ---------------- host ----------------
extern "C" void kernel_launch(void* const* d_in, const int* in_sizes, int n_in,
                              void* d_out, int out_size) {
    const float* x    = (const float*)d_in[0];
    const float* q    = (const float*)d_in[1];
    const float* fc_w = (const float*)d_in[2];
    const float* fc_b = (const float*)d_in[3];
    float* out = (float*)d_out;

    prep_kernel<<<(BB * TT + LL) / 8, 256>>>(x, q, fc_w);

    cudaFuncSetAttribute(attn_kernel, cudaFuncAttributeMaxDynamicSharedMemorySize, SMEM_TOTAL);
    attn_kernel<<<dim3(LL / TILE_M, BB), NTHREADS, SMEM_TOTAL>>>(fc_b, out);
}